// round 2
// baseline (speedup 1.0000x reference)
#include <cuda_runtime.h>

// Problem constants
#define KCODES 1024
#define CD     64
#define NPIX   131072            // 32 * 64 * 64
#define HW     4096              // 64 * 64
#define CHUNK  128               // codes per smem tile (128*64*4B = 32 KB)
#define TPB    256
#define O_ELEMS  8388608         // NPIX * CD
#define LOSS_OFF 8388608
#define IDX_OFF  8388609

__device__ float g_halfnorm[KCODES];
__device__ float g_loss;

// -------- prep: half-norms of codebook rows + zero the loss accumulator ----
__global__ void vq_prep(const float* __restrict__ emb) {
    int k = blockIdx.x * blockDim.x + threadIdx.x;
    if (k == 0) g_loss = 0.f;
    if (k < KCODES) {
        const float4* row = (const float4*)(emb + (size_t)k * CD);
        float s = 0.f;
#pragma unroll
        for (int i = 0; i < CD / 4; i++) {
            float4 v = row[i];
            s += v.x * v.x + v.y * v.y + v.z * v.z + v.w * v.w;
        }
        g_halfnorm[k] = 0.5f * s;
    }
}

// -------- main: argmin over codebook + straight-through output + loss ------
__global__ __launch_bounds__(TPB, 2)
void vq_main(const float* __restrict__ x, const float* __restrict__ emb,
             float* __restrict__ out, int out_size)
{
    __shared__ __align__(16) float s_emb[CHUNK * CD];   // 32 KB
    __shared__ float s_hn[CHUNK];
    __shared__ float s_red[TPB / 32];

    const int tid = threadIdx.x;
    const int n   = blockIdx.x * TPB + tid;   // pixel id; block never crosses b
    const int b   = n >> 12;
    const int hw  = n & (HW - 1);
    const float* xz = x + ((size_t)b * CD) * HW + hw;   // component c at xz[c*HW]

    // Load z into registers as 32 packed f32x2 pairs (c = 2i, 2i+1)
    unsigned long long zp[CD / 2];
#pragma unroll
    for (int i = 0; i < CD / 2; i++) {
        float a = __ldg(xz + (2 * i) * HW);
        float c = __ldg(xz + (2 * i + 1) * HW);
        asm("mov.b64 %0, {%1, %2};" : "=l"(zp[i]) : "f"(a), "f"(c));
    }

    float best = 3.402823466e38f;
    int   bi   = 0;

    for (int k0 = 0; k0 < KCODES; k0 += CHUNK) {
        __syncthreads();
        // Cooperative smem fill: 2048 float4 over 256 threads = 8 each
        const float4* g4 = (const float4*)(emb + (size_t)k0 * CD);
        float4* s4 = (float4*)s_emb;
#pragma unroll
        for (int i = 0; i < (CHUNK * CD / 4) / TPB; i++)
            s4[tid + i * TPB] = g4[tid + i * TPB];
        if (tid < CHUNK) s_hn[tid] = g_halfnorm[k0 + tid];
        __syncthreads();

#pragma unroll 2
        for (int kk = 0; kk < CHUNK; kk++) {
            const ulonglong2* e2 = (const ulonglong2*)(s_emb + kk * CD);
            unsigned long long acc0 = 0ULL, acc1 = 0ULL;  // packed {0.f, 0.f}
#pragma unroll
            for (int i = 0; i < CD / 4; i++) {
                ulonglong2 ev = e2[i];   // LDS.128, broadcast across warp
                asm("fma.rn.f32x2 %0, %1, %2, %0;"
                    : "+l"(acc0) : "l"(zp[2 * i]),     "l"(ev.x));
                asm("fma.rn.f32x2 %0, %1, %2, %0;"
                    : "+l"(acc1) : "l"(zp[2 * i + 1]), "l"(ev.y));
            }
            float l0, h0, l1, h1;
            asm("mov.b64 {%0, %1}, %2;" : "=f"(l0), "=f"(h0) : "l"(acc0));
            asm("mov.b64 {%0, %1}, %2;" : "=f"(l1), "=f"(h1) : "l"(acc1));
            float dot   = (l0 + h0) + (l1 + h1);
            float score = s_hn[kk] - dot;       // 0.5||e||^2 - z.e
            if (score < best) { best = score; bi = k0 + kk; }  // first-min tiebreak
        }
    }

    // -------- epilogue: gather e, write o = x + (e - x), accumulate loss ---
    const float4* erow = (const float4*)(emb + (size_t)bi * CD);
    float lsum = 0.f;
#pragma unroll
    for (int i = 0; i < CD / 4; i++) {
        float4 ev = erow[i];            // L2-resident gather, 16B per load
        float x0, x1, x2, x3;
        asm("mov.b64 {%0, %1}, %2;" : "=f"(x0), "=f"(x1) : "l"(zp[2 * i]));
        asm("mov.b64 {%0, %1}, %2;" : "=f"(x2), "=f"(x3) : "l"(zp[2 * i + 1]));

        size_t base = ((size_t)b * CD + 4 * i) * HW + hw;
        out[base]          = x0 + (ev.x - x0);   // mimic reference rounding
        out[base + HW]     = x1 + (ev.y - x1);
        out[base + 2 * HW] = x2 + (ev.z - x2);
        out[base + 3 * HW] = x3 + (ev.w - x3);

        float d0 = x0 - ev.x, d1 = x1 - ev.y, d2 = x2 - ev.z, d3 = x3 - ev.w;
        lsum += d0 * d0 + d1 * d1 + d2 * d2 + d3 * d3;
    }

    // loss block-reduce -> single atomic per block
#pragma unroll
    for (int off = 16; off > 0; off >>= 1)
        lsum += __shfl_down_sync(0xffffffffu, lsum, off);
    if ((tid & 31) == 0) s_red[tid >> 5] = lsum;
    __syncthreads();
    if (tid < TPB / 32) {
        float v = s_red[tid];
#pragma unroll
        for (int off = 4; off > 0; off >>= 1)
            v += __shfl_down_sync(0x000000ffu, v, off);
        if (tid == 0) atomicAdd(&g_loss, v);
    }

    // indices (as float, after o and loss slots)
    if (IDX_OFF + n < out_size) out[IDX_OFF + n] = (float)bi;
}

// -------- finalize: scalar loss = 1.25 * mean((x-e)^2) ---------------------
__global__ void vq_fin(float* out, int out_size) {
    if (out_size > LOSS_OFF)
        out[LOSS_OFF] = 1.25f * g_loss * (1.0f / 8388608.0f);
}

extern "C" void kernel_launch(void* const* d_in, const int* in_sizes, int n_in,
                              void* d_out, int out_size) {
    const float* x   = (const float*)d_in[0];
    const float* emb = (const float*)d_in[1];
    float* out = (float*)d_out;

    vq_prep<<<(KCODES + 255) / 256, 256>>>(emb);
    vq_main<<<NPIX / TPB, TPB>>>(x, emb, out, out_size);
    vq_fin<<<1, 1>>>(out, out_size);
}

// round 3
// speedup vs baseline: 1.0002x; 1.0002x over previous
#include <cuda_runtime.h>

// Problem constants
#define KCODES 1024
#define CD     64
#define NPIX   131072            // 32 * 64 * 64
#define HW     4096              // 64 * 64
#define CHUNK  128               // codes per smem tile (128*64*4B = 32 KB)
#define TPB    256
#define O_ELEMS  8388608         // NPIX * CD
#define LOSS_OFF 8388608
#define IDX_OFF  8388609

__device__ float g_halfnorm[KCODES];
__device__ float g_loss;

// -------- prep: half-norms of codebook rows + zero the loss accumulator ----
__global__ void vq_prep(const float* __restrict__ emb) {
    int k = blockIdx.x * blockDim.x + threadIdx.x;
    if (k == 0) g_loss = 0.f;
    if (k < KCODES) {
        const float4* row = (const float4*)(emb + (size_t)k * CD);
        float s = 0.f;
#pragma unroll
        for (int i = 0; i < CD / 4; i++) {
            float4 v = row[i];
            s += v.x * v.x + v.y * v.y + v.z * v.z + v.w * v.w;
        }
        g_halfnorm[k] = 0.5f * s;
    }
}

// -------- main: argmin over codebook + straight-through output + loss ------
__global__ __launch_bounds__(TPB, 2)
void vq_main(const float* __restrict__ x, const float* __restrict__ emb,
             float* __restrict__ out, int out_size)
{
    __shared__ __align__(16) float s_emb[CHUNK * CD];   // 32 KB
    __shared__ float s_hn[CHUNK];
    __shared__ float s_red[TPB / 32];

    const int tid = threadIdx.x;
    const int n   = blockIdx.x * TPB + tid;   // pixel id; block never crosses b
    const int b   = n >> 12;
    const int hw  = n & (HW - 1);
    const float* xz = x + ((size_t)b * CD) * HW + hw;   // component c at xz[c*HW]

    // Load z into registers as 32 packed f32x2 pairs (c = 2i, 2i+1)
    unsigned long long zp[CD / 2];
#pragma unroll
    for (int i = 0; i < CD / 2; i++) {
        float a = __ldg(xz + (2 * i) * HW);
        float c = __ldg(xz + (2 * i + 1) * HW);
        asm("mov.b64 %0, {%1, %2};" : "=l"(zp[i]) : "f"(a), "f"(c));
    }

    float best = 3.402823466e38f;
    int   bi   = 0;

    for (int k0 = 0; k0 < KCODES; k0 += CHUNK) {
        __syncthreads();
        // Cooperative smem fill: 2048 float4 over 256 threads = 8 each
        const float4* g4 = (const float4*)(emb + (size_t)k0 * CD);
        float4* s4 = (float4*)s_emb;
#pragma unroll
        for (int i = 0; i < (CHUNK * CD / 4) / TPB; i++)
            s4[tid + i * TPB] = g4[tid + i * TPB];
        if (tid < CHUNK) s_hn[tid] = g_halfnorm[k0 + tid];
        __syncthreads();

#pragma unroll 2
        for (int kk = 0; kk < CHUNK; kk++) {
            const ulonglong2* e2 = (const ulonglong2*)(s_emb + kk * CD);
            unsigned long long acc0 = 0ULL, acc1 = 0ULL;  // packed {0.f, 0.f}
#pragma unroll
            for (int i = 0; i < CD / 4; i++) {
                ulonglong2 ev = e2[i];   // LDS.128, broadcast across warp
                asm("fma.rn.f32x2 %0, %1, %2, %0;"
                    : "+l"(acc0) : "l"(zp[2 * i]),     "l"(ev.x));
                asm("fma.rn.f32x2 %0, %1, %2, %0;"
                    : "+l"(acc1) : "l"(zp[2 * i + 1]), "l"(ev.y));
            }
            float l0, h0, l1, h1;
            asm("mov.b64 {%0, %1}, %2;" : "=f"(l0), "=f"(h0) : "l"(acc0));
            asm("mov.b64 {%0, %1}, %2;" : "=f"(l1), "=f"(h1) : "l"(acc1));
            float dot   = (l0 + h0) + (l1 + h1);
            float score = s_hn[kk] - dot;       // 0.5||e||^2 - z.e
            if (score < best) { best = score; bi = k0 + kk; }  // first-min tiebreak
        }
    }

    // -------- epilogue: gather e, write o = x + (e - x), accumulate loss ---
    const float4* erow = (const float4*)(emb + (size_t)bi * CD);
    float lsum = 0.f;
#pragma unroll
    for (int i = 0; i < CD / 4; i++) {
        float4 ev = erow[i];            // L2-resident gather, 16B per load
        float x0, x1, x2, x3;
        asm("mov.b64 {%0, %1}, %2;" : "=f"(x0), "=f"(x1) : "l"(zp[2 * i]));
        asm("mov.b64 {%0, %1}, %2;" : "=f"(x2), "=f"(x3) : "l"(zp[2 * i + 1]));

        size_t base = ((size_t)b * CD + 4 * i) * HW + hw;
        out[base]          = x0 + (ev.x - x0);   // mimic reference rounding
        out[base + HW]     = x1 + (ev.y - x1);
        out[base + 2 * HW] = x2 + (ev.z - x2);
        out[base + 3 * HW] = x3 + (ev.w - x3);

        float d0 = x0 - ev.x, d1 = x1 - ev.y, d2 = x2 - ev.z, d3 = x3 - ev.w;
        lsum += d0 * d0 + d1 * d1 + d2 * d2 + d3 * d3;
    }

    // loss block-reduce -> single atomic per block
#pragma unroll
    for (int off = 16; off > 0; off >>= 1)
        lsum += __shfl_down_sync(0xffffffffu, lsum, off);
    if ((tid & 31) == 0) s_red[tid >> 5] = lsum;
    __syncthreads();
    if (tid < TPB / 32) {
        float v = s_red[tid];
#pragma unroll
        for (int off = 4; off > 0; off >>= 1)
            v += __shfl_down_sync(0x000000ffu, v, off);
        if (tid == 0) atomicAdd(&g_loss, v);
    }

    // indices (as float, after o and loss slots)
    if (IDX_OFF + n < out_size) out[IDX_OFF + n] = (float)bi;
}

// -------- finalize: scalar loss = 1.25 * mean((x-e)^2) ---------------------
__global__ void vq_fin(float* out, int out_size) {
    if (out_size > LOSS_OFF)
        out[LOSS_OFF] = 1.25f * g_loss * (1.0f / 8388608.0f);
}

extern "C" void kernel_launch(void* const* d_in, const int* in_sizes, int n_in,
                              void* d_out, int out_size) {
    const float* x   = (const float*)d_in[0];
    const float* emb = (const float*)d_in[1];
    float* out = (float*)d_out;

    vq_prep<<<(KCODES + 255) / 256, 256>>>(emb);
    vq_main<<<NPIX / TPB, TPB>>>(x, emb, out, out_size);
    vq_fin<<<1, 1>>>(out, out_size);
}

// round 8
// speedup vs baseline: 2.7332x; 2.7327x over previous
#include <cuda_runtime.h>
#include <cuda_bf16.h>
#include <cstdint>
#include <cstring>

#define KCODES 1024
#define CD     64
#define NPIX   131072
#define HWDIM  4096
#define TPB    256
#define LOSS_OFF 8388608
#define IDX_OFF  8388609
#define NCHUNK 16            // 16 chunks x 64 codes
#define TPC    8             // tiles (of 8 codes) per chunk
#define EPS    1e-2f
#define NCAND  12

__device__ float g_halfnorm[KCODES];
__device__ float g_loss;
// fragment-ordered codebook: [tile(128)][lane(32)][2 x uint4]  (hi and lo parts)
__device__ __align__(16) uint4 g_Bh[128 * 32 * 2];
__device__ __align__(16) uint4 g_Bl[128 * 32 * 2];

static __device__ __forceinline__ uint32_t smem_u32(const void* p) {
    uint32_t a;
    asm("{ .reg .u64 t; cvta.to.shared.u64 t, %1; cvt.u32.u64 %0, t; }" : "=r"(a) : "l"(p));
    return a;
}
static __device__ __forceinline__ void cp_async16(uint32_t s, const void* g) {
    asm volatile("cp.async.ca.shared.global [%0], [%1], 16;" :: "r"(s), "l"(g) : "memory");
}
static __device__ __forceinline__ uint32_t bpack(float a, float b, float& ra, float& rb) {
    __nv_bfloat162 h = __floats2bfloat162_rn(a, b);
    ra = a - __bfloat162float(h.x);
    rb = b - __bfloat162float(h.y);
    uint32_t u; memcpy(&u, &h, 4); return u;
}
static __device__ __forceinline__ uint32_t bpack2(float a, float b) {
    __nv_bfloat162 h = __floats2bfloat162_rn(a, b);
    uint32_t u; memcpy(&u, &h, 4); return u;
}

#define MMA(d, a, bx, by)                                                          \
    asm volatile("mma.sync.aligned.m16n8k16.row.col.f32.bf16.bf16.f32 "            \
        "{%0,%1,%2,%3},{%4,%5,%6,%7},{%8,%9},{%0,%1,%2,%3};"                       \
        : "+f"(d[0]), "+f"(d[1]), "+f"(d[2]), "+f"(d[3])                           \
        : "r"(a[0]), "r"(a[1]), "r"(a[2]), "r"(a[3]), "r"(bx), "r"(by))

// per-lane top-3, first-index tie-break (ascending n scan, strict <)
#define UPD(p, v, n)                                                               \
    { float _v = (v);                                                              \
      if (_v < tt[p]) {                                                            \
        if (_v < ss[p]) {                                                          \
          if (_v < bb[p]) { tt[p]=ss[p]; kk[p]=jj[p]; ss[p]=bb[p]; jj[p]=ii[p];    \
                            bb[p]=_v; ii[p]=(n); }                                 \
          else            { tt[p]=ss[p]; kk[p]=jj[p]; ss[p]=_v; jj[p]=(n); }       \
        } else            { tt[p]=_v; kk[p]=(n); } } }

// ---- prep: halfnorms (R1-replica arithmetic) + fragment-ordered codebook ----
__global__ void vq_prep(const float* __restrict__ emb) {
    int t = blockIdx.x * blockDim.x + threadIdx.x;   // 4096 threads
    if (t == 0) g_loss = 0.f;
    if (t < KCODES) {
        const float4* row = (const float4*)(emb + (size_t)t * CD);
        float s = 0.f;
#pragma unroll
        for (int i = 0; i < CD / 4; i++) {
            float4 v = row[i];
            s += v.x * v.x + v.y * v.y + v.z * v.z + v.w * v.w;
        }
        g_halfnorm[t] = 0.5f * s;
    }
    int tile = t >> 5, l = t & 31, g = l >> 2, m = l & 3;
    int code = tile * 8 + g;
    const float* e = emb + (size_t)code * CD;
    uint32_t h[8], lo[8];
#pragma unroll
    for (int s = 0; s < 4; s++) {
        int c0 = 16 * s + 2 * m;
        float r0, r1, r2, r3;
        h[2 * s]     = bpack(e[c0],     e[c0 + 1], r0, r1);
        h[2 * s + 1] = bpack(e[c0 + 8], e[c0 + 9], r2, r3);
        lo[2 * s]     = bpack2(r0, r1);
        lo[2 * s + 1] = bpack2(r2, r3);
    }
    int base = (tile * 32 + l) * 2;
    g_Bh[base]     = make_uint4(h[0], h[1], h[2], h[3]);
    g_Bh[base + 1] = make_uint4(h[4], h[5], h[6], h[7]);
    g_Bl[base]     = make_uint4(lo[0], lo[1], lo[2], lo[3]);
    g_Bl[base + 1] = make_uint4(lo[4], lo[5], lo[6], lo[7]);
}

// ---- main: HMMA distance field + per-lane top-3 + exact R1-replica rescue ----
__global__ __launch_bounds__(TPB, 2)
void vq_mma(const float* __restrict__ x, const float* __restrict__ emb,
            float* __restrict__ out, int out_size)
{
    // 32 KB pool: B double-buffer during main loop; candidate arrays afterwards
    __shared__ __align__(16) unsigned char s_pool[32768];
    __shared__ float s_hn[KCODES];
    __shared__ float s_red[8];

    const int tid = threadIdx.x;
    const int w = tid >> 5, l = tid & 31, g = l >> 2, m = l & 3;
    const int blockpix = blockIdx.x << 8;
    const int b = blockpix >> 12;
    const int hwbase = (blockpix & (HWDIM - 1)) + (w << 5);
    const float* xb = x + (size_t)b * CD * HWDIM;

    // ---- build A fragments (negated z, bf16 hi + lo residual) ----
    uint32_t ah[2][4][4], al[2][4][4];
#pragma unroll
    for (int ri = 0; ri < 4; ri++) {
        const int mt = ri >> 1, rr = ri & 1;
        const float* xp = xb + hwbase + g + rr * 8 + mt * 16;
#pragma unroll
        for (int s = 0; s < 4; s++) {
            int c0 = 16 * s + 2 * m;
            float f0 = -__ldg(xp + (size_t)c0 * HWDIM);
            float f1 = -__ldg(xp + (size_t)(c0 + 1) * HWDIM);
            float f2 = -__ldg(xp + (size_t)(c0 + 8) * HWDIM);
            float f3 = -__ldg(xp + (size_t)(c0 + 9) * HWDIM);
            float r0, r1, r2, r3;
            ah[mt][s][rr]     = bpack(f0, f1, r0, r1);
            ah[mt][s][2 + rr] = bpack(f2, f3, r2, r3);
            al[mt][s][rr]     = bpack2(r0, r1);
            al[mt][s][2 + rr] = bpack2(r2, r3);
        }
    }

    // halfnorms to smem
#pragma unroll
    for (int i = 0; i < 4; i++) s_hn[tid + i * TPB] = g_halfnorm[tid + i * TPB];

    // prefetch chunk 0 (hi at pool+buf*8K, lo at pool+16K+buf*8K)
    {
        uint32_t dh = smem_u32(s_pool) + tid * 32;
        uint32_t dl = dh + 16384;
        const uint4* sh = g_Bh + tid * 2;
        const uint4* sl = g_Bl + tid * 2;
        cp_async16(dh, sh); cp_async16(dh + 16, sh + 1);
        cp_async16(dl, sl); cp_async16(dl + 16, sl + 1);
        asm volatile("cp.async.commit_group;" ::: "memory");
    }
    asm volatile("cp.async.wait_group 0;" ::: "memory");
    __syncthreads();

    float bb[4] = {3.4e38f, 3.4e38f, 3.4e38f, 3.4e38f};
    float ss[4] = {3.4e38f, 3.4e38f, 3.4e38f, 3.4e38f};
    float tt[4] = {3.4e38f, 3.4e38f, 3.4e38f, 3.4e38f};
    int ii[4] = {0,0,0,0}, jj[4] = {0,0,0,0}, kk[4] = {0,0,0,0};

#pragma unroll 1
    for (int ch = 0; ch < NCHUNK; ch++) {
        const int buf = ch & 1;
        if (ch + 1 < NCHUNK) {   // async prefetch next chunk
            const int nb = buf ^ 1;
            uint32_t dh = smem_u32(s_pool) + nb * 8192 + tid * 32;
            uint32_t dl = dh + 16384;
            const uint4* sh = g_Bh + (ch + 1) * 512 + tid * 2;
            const uint4* sl = g_Bl + (ch + 1) * 512 + tid * 2;
            cp_async16(dh, sh); cp_async16(dh + 16, sh + 1);
            cp_async16(dl, sl); cp_async16(dl + 16, sl + 1);
            asm volatile("cp.async.commit_group;" ::: "memory");
        }

        const uint4* bhp = (const uint4*)(s_pool + buf * 8192);
        const uint4* blp = (const uint4*)(s_pool + 16384 + buf * 8192);
#pragma unroll
        for (int t = 0; t < TPC; t++) {
            uint4 h0 = bhp[t * 64 + l * 2];
            uint4 h1 = bhp[t * 64 + l * 2 + 1];
            uint4 q0 = blp[t * 64 + l * 2];
            uint4 q1 = blp[t * 64 + l * 2 + 1];
            const int n0 = ch * 64 + t * 8 + 2 * m;
            float2 hp = *(const float2*)&s_hn[n0];

            float d0[4], d1[4];
            d0[0] = hp.x; d0[1] = hp.y; d0[2] = hp.x; d0[3] = hp.y;
            d1[0] = hp.x; d1[1] = hp.y; d1[2] = hp.x; d1[3] = hp.y;

            // term 1: (-zh) . eh
            MMA(d0, ah[0][0], h0.x, h0.y); MMA(d1, ah[1][0], h0.x, h0.y);
            MMA(d0, ah[0][1], h0.z, h0.w); MMA(d1, ah[1][1], h0.z, h0.w);
            MMA(d0, ah[0][2], h1.x, h1.y); MMA(d1, ah[1][2], h1.x, h1.y);
            MMA(d0, ah[0][3], h1.z, h1.w); MMA(d1, ah[1][3], h1.z, h1.w);
            // term 2: (-zh) . el
            MMA(d0, ah[0][0], q0.x, q0.y); MMA(d1, ah[1][0], q0.x, q0.y);
            MMA(d0, ah[0][1], q0.z, q0.w); MMA(d1, ah[1][1], q0.z, q0.w);
            MMA(d0, ah[0][2], q1.x, q1.y); MMA(d1, ah[1][2], q1.x, q1.y);
            MMA(d0, ah[0][3], q1.z, q1.w); MMA(d1, ah[1][3], q1.z, q1.w);
            // term 3: (-zl) . eh
            MMA(d0, al[0][0], h0.x, h0.y); MMA(d1, al[1][0], h0.x, h0.y);
            MMA(d0, al[0][1], h0.z, h0.w); MMA(d1, al[1][1], h0.z, h0.w);
            MMA(d0, al[0][2], h1.x, h1.y); MMA(d1, al[1][2], h1.x, h1.y);
            MMA(d0, al[0][3], h1.z, h1.w); MMA(d1, al[1][3], h1.z, h1.w);

            UPD(0, d0[0], n0); UPD(0, d0[1], n0 + 1);
            UPD(1, d0[2], n0); UPD(1, d0[3], n0 + 1);
            UPD(2, d1[0], n0); UPD(2, d1[1], n0 + 1);
            UPD(3, d1[2], n0); UPD(3, d1[3], n0 + 1);
        }
        asm volatile("cp.async.wait_group 0;" ::: "memory");
        __syncthreads();
    }

    // ---- dump all 12 per-pixel candidates (4 lanes x top-3) into the pool ----
    int   (*s_cand)[NCAND] = (int(*)[NCAND])s_pool;                  // 12 KB
    float (*s_scA)[NCAND]  = (float(*)[NCAND])(s_pool + 12288);     // 12 KB
#pragma unroll
    for (int p = 0; p < 4; p++) {
        int row = g + (p & 1) * 8 + (p >> 1) * 16;
        int pr = w * 32 + row;
        s_cand[pr][3 * m]     = ii[p];
        s_cand[pr][3 * m + 1] = jj[p];
        s_cand[pr][3 * m + 2] = kk[p];
        s_scA[pr][3 * m]      = bb[p];
        s_scA[pr][3 * m + 1]  = ss[p];
        s_scA[pr][3 * m + 2]  = tt[p];
    }
    __syncthreads();

    // ---- per-pixel exact rescue (R1-replica comparator) ----
    const int pixel = blockpix + tid;
    const int hw = pixel & (HWDIM - 1);
    const float* xp = xb + hw;
    float z[CD];
#pragma unroll
    for (int c = 0; c < CD; c++) z[c] = __ldg(xp + (size_t)c * HWDIM);

    int   cand[NCAND];
    float sc[NCAND];
#pragma unroll
    for (int i = 0; i < NCAND; i++) { cand[i] = s_cand[tid][i]; sc[i] = s_scA[tid][i]; }

    // approx-min with first-index tie-break
    float mb = sc[0]; int win = cand[0];
#pragma unroll
    for (int i = 1; i < NCAND; i++)
        if (sc[i] < mb || (sc[i] == mb && cand[i] < win)) { mb = sc[i]; win = cand[i]; }

    int nq = 0;
#pragma unroll
    for (int i = 0; i < NCAND; i++) nq += (sc[i] <= mb + EPS);
    if (nq > 1) {
        // exact rescoring with R1's exact arithmetic: 4 independent fma chains
        // over channels c%4, merged (p0+p1)+(p2+p3); score = hn - dot
        float be = 3.4e38f; int bw = 0x7fffffff;
#pragma unroll 1
        for (int i = 0; i < NCAND; i++) {
            if (sc[i] <= mb + EPS) {
                const float* er = emb + (size_t)cand[i] * CD;
                float p0 = 0.f, p1 = 0.f, p2 = 0.f, p3 = 0.f;
#pragma unroll
                for (int q = 0; q < CD / 4; q++) {
                    p0 = fmaf(z[4*q],     er[4*q],     p0);
                    p1 = fmaf(z[4*q + 1], er[4*q + 1], p1);
                    p2 = fmaf(z[4*q + 2], er[4*q + 2], p2);
                    p3 = fmaf(z[4*q + 3], er[4*q + 3], p3);
                }
                float dot = __fadd_rn(__fadd_rn(p0, p1), __fadd_rn(p2, p3));
                float se  = __fsub_rn(s_hn[cand[i]], dot);
                if (se < be || (se == be && cand[i] < bw)) { be = se; bw = cand[i]; }
            }
        }
        win = bw;
    }

    // ---- outputs ----
    const float4* erow = (const float4*)(emb + (size_t)win * CD);
    float lsum = 0.f;
#pragma unroll
    for (int i = 0; i < CD / 4; i++) {
        float4 ev = erow[i];
        float x0 = z[4*i], x1 = z[4*i+1], x2 = z[4*i+2], x3 = z[4*i+3];
        size_t base = ((size_t)b * CD + 4 * i) * HWDIM + hw;
        out[base]             = x0 + (ev.x - x0);
        out[base + HWDIM]     = x1 + (ev.y - x1);
        out[base + 2 * HWDIM] = x2 + (ev.z - x2);
        out[base + 3 * HWDIM] = x3 + (ev.w - x3);
        float e0 = x0 - ev.x, e1 = x1 - ev.y, e2 = x2 - ev.z, e3 = x3 - ev.w;
        lsum += e0 * e0 + e1 * e1 + e2 * e2 + e3 * e3;
    }
#pragma unroll
    for (int off = 16; off > 0; off >>= 1)
        lsum += __shfl_down_sync(0xffffffffu, lsum, off);
    if (l == 0) s_red[w] = lsum;
    __syncthreads();
    if (tid < 8) {
        float v = s_red[tid];
#pragma unroll
        for (int off = 4; off > 0; off >>= 1)
            v += __shfl_down_sync(0x000000ffu, v, off);
        if (tid == 0) atomicAdd(&g_loss, v);
    }
    if (IDX_OFF + pixel < out_size) out[IDX_OFF + pixel] = (float)win;
}

__global__ void vq_fin(float* out, int out_size) {
    if (out_size > LOSS_OFF)
        out[LOSS_OFF] = 1.25f * g_loss * (1.0f / 8388608.0f);
}

extern "C" void kernel_launch(void* const* d_in, const int* in_sizes, int n_in,
                              void* d_out, int out_size) {
    const float* x   = (const float*)d_in[0];
    const float* emb = (const float*)d_in[1];
    float* out = (float*)d_out;

    vq_prep<<<16, 256>>>(emb);
    vq_mma<<<NPIX / TPB, TPB>>>(x, emb, out, out_size);
    vq_fin<<<1, 1>>>(out, out_size);
}

// round 9
// speedup vs baseline: 2.9004x; 1.0612x over previous
#include <cuda_runtime.h>
#include <cuda_fp16.h>
#include <cstdint>
#include <cstring>

#define KCODES 1024
#define CD     64
#define NPIX   131072
#define HWDIM  4096
#define TPB    256
#define LOSS_OFF 8388608
#define IDX_OFF  8388609
#define NCHUNK 16            // 16 chunks x 64 codes
#define TPC    8             // tiles (of 8 codes) per chunk
#define EPS    0.25f
#define NCAND  16

__device__ float g_halfnorm[KCODES];
__device__ float g_loss;
// fragment-ordered fp16 codebook: [tile(128)][lane(32)][2 x uint4]
__device__ __align__(16) uint4 g_Bh[128 * 32 * 2];

static __device__ __forceinline__ uint32_t smem_u32(const void* p) {
    uint32_t a;
    asm("{ .reg .u64 t; cvta.to.shared.u64 t, %1; cvt.u32.u64 %0, t; }" : "=r"(a) : "l"(p));
    return a;
}
static __device__ __forceinline__ void cp_async16(uint32_t s, const void* g) {
    asm volatile("cp.async.ca.shared.global [%0], [%1], 16;" :: "r"(s), "l"(g) : "memory");
}
static __device__ __forceinline__ uint32_t hpack(float a, float b) {
    __half2 h = __floats2half2_rn(a, b);
    uint32_t u; memcpy(&u, &h, 4); return u;
}

#define MMA(d, a, bx, by)                                                          \
    asm volatile("mma.sync.aligned.m16n8k16.row.col.f32.f16.f16.f32 "              \
        "{%0,%1,%2,%3},{%4,%5,%6,%7},{%8,%9},{%0,%1,%2,%3};"                       \
        : "+f"(d[0]), "+f"(d[1]), "+f"(d[2]), "+f"(d[3])                           \
        : "r"(a[0]), "r"(a[1]), "r"(a[2]), "r"(a[3]), "r"(bx), "r"(by))

// per-lane top-4, first-index tie-break (ascending n scan, strict <)
#define UPD(p, v, n)                                                               \
    { float _v = (v);                                                              \
      if (_v < qq[p]) {                                                            \
        if (_v < tt[p]) {                                                          \
          if (_v < ss[p]) {                                                        \
            if (_v < bb[p]) { qq[p]=tt[p]; ll[p]=kk[p]; tt[p]=ss[p]; kk[p]=jj[p];  \
                              ss[p]=bb[p]; jj[p]=ii[p]; bb[p]=_v; ii[p]=(n); }     \
            else { qq[p]=tt[p]; ll[p]=kk[p]; tt[p]=ss[p]; kk[p]=jj[p];             \
                   ss[p]=_v; jj[p]=(n); }                                          \
          } else { qq[p]=tt[p]; ll[p]=kk[p]; tt[p]=_v; kk[p]=(n); }                \
        } else { qq[p]=_v; ll[p]=(n); } } }

// ---- prep: halfnorms (R1-replica arithmetic) + fragment-ordered fp16 codebook --
__global__ void vq_prep(const float* __restrict__ emb) {
    int t = blockIdx.x * blockDim.x + threadIdx.x;   // 4096 threads
    if (t == 0) g_loss = 0.f;
    if (t < KCODES) {
        const float4* row = (const float4*)(emb + (size_t)t * CD);
        float s = 0.f;
#pragma unroll
        for (int i = 0; i < CD / 4; i++) {
            float4 v = row[i];
            s += v.x * v.x + v.y * v.y + v.z * v.z + v.w * v.w;
        }
        g_halfnorm[t] = 0.5f * s;
    }
    int tile = t >> 5, l = t & 31, m = l & 3;
    int code = tile * 8 + (l >> 2);
    const float* e = emb + (size_t)code * CD;
    uint32_t h[8];
#pragma unroll
    for (int s = 0; s < 4; s++) {
        int c0 = 16 * s + 2 * m;
        h[2 * s]     = hpack(e[c0],     e[c0 + 1]);
        h[2 * s + 1] = hpack(e[c0 + 8], e[c0 + 9]);
    }
    int base = (tile * 32 + l) * 2;
    g_Bh[base]     = make_uint4(h[0], h[1], h[2], h[3]);
    g_Bh[base + 1] = make_uint4(h[4], h[5], h[6], h[7]);
}

// ---- main: fp16 HMMA screen + per-lane top-4 + exact R1-replica rescue ----
__global__ __launch_bounds__(TPB, 2)
void vq_mma(const float* __restrict__ x, const float* __restrict__ emb,
            float* __restrict__ out, int out_size)
{
    // 32 KB pool: B double-buffer (2 x 8 KB) during loop; candidates afterwards
    __shared__ __align__(16) unsigned char s_pool[32768];
    __shared__ float s_hn[KCODES];
    __shared__ float s_red[8];

    const int tid = threadIdx.x;
    const int w = tid >> 5, l = tid & 31, g = l >> 2, m = l & 3;
    const int blockpix = blockIdx.x << 8;
    const int b = blockpix >> 12;
    const int hwbase = (blockpix & (HWDIM - 1)) + (w << 5);
    const float* xb = x + (size_t)b * CD * HWDIM;

    // ---- build A fragments (negated z, fp16) ----
    uint32_t ah[2][4][4];
#pragma unroll
    for (int ri = 0; ri < 4; ri++) {
        const int mt = ri >> 1, rr = ri & 1;
        const float* xp = xb + hwbase + g + rr * 8 + mt * 16;
#pragma unroll
        for (int s = 0; s < 4; s++) {
            int c0 = 16 * s + 2 * m;
            float f0 = -__ldg(xp + (size_t)c0 * HWDIM);
            float f1 = -__ldg(xp + (size_t)(c0 + 1) * HWDIM);
            float f2 = -__ldg(xp + (size_t)(c0 + 8) * HWDIM);
            float f3 = -__ldg(xp + (size_t)(c0 + 9) * HWDIM);
            ah[mt][s][rr]     = hpack(f0, f1);
            ah[mt][s][2 + rr] = hpack(f2, f3);
        }
    }

    // halfnorms to smem
#pragma unroll
    for (int i = 0; i < 4; i++) s_hn[tid + i * TPB] = g_halfnorm[tid + i * TPB];

    // prefetch chunk 0 (8 KB: 2 uint4 per thread)
    {
        uint32_t dh = smem_u32(s_pool) + tid * 32;
        const uint4* sh = g_Bh + tid * 2;
        cp_async16(dh, sh); cp_async16(dh + 16, sh + 1);
        asm volatile("cp.async.commit_group;" ::: "memory");
    }
    asm volatile("cp.async.wait_group 0;" ::: "memory");
    __syncthreads();

    float bb[4] = {3.4e38f,3.4e38f,3.4e38f,3.4e38f};
    float ss[4] = {3.4e38f,3.4e38f,3.4e38f,3.4e38f};
    float tt[4] = {3.4e38f,3.4e38f,3.4e38f,3.4e38f};
    float qq[4] = {3.4e38f,3.4e38f,3.4e38f,3.4e38f};
    int ii[4] = {0,0,0,0}, jj[4] = {0,0,0,0}, kk[4] = {0,0,0,0}, ll[4] = {0,0,0,0};

#pragma unroll 1
    for (int ch = 0; ch < NCHUNK; ch++) {
        const int buf = ch & 1;
        if (ch + 1 < NCHUNK) {   // async prefetch next chunk
            uint32_t dh = smem_u32(s_pool) + (buf ^ 1) * 8192 + tid * 32;
            const uint4* sh = g_Bh + (ch + 1) * 512 + tid * 2;
            cp_async16(dh, sh); cp_async16(dh + 16, sh + 1);
            asm volatile("cp.async.commit_group;" ::: "memory");
        }

        const uint4* bhp = (const uint4*)(s_pool + buf * 8192);
#pragma unroll
        for (int t = 0; t < TPC; t++) {
            uint4 h0 = bhp[t * 64 + l * 2];
            uint4 h1 = bhp[t * 64 + l * 2 + 1];
            const int n0 = ch * 64 + t * 8 + 2 * m;
            float2 hp = *(const float2*)&s_hn[n0];

            float d0[4], d1[4];
            d0[0] = hp.x; d0[1] = hp.y; d0[2] = hp.x; d0[3] = hp.y;
            d1[0] = hp.x; d1[1] = hp.y; d1[2] = hp.x; d1[3] = hp.y;

            MMA(d0, ah[0][0], h0.x, h0.y); MMA(d1, ah[1][0], h0.x, h0.y);
            MMA(d0, ah[0][1], h0.z, h0.w); MMA(d1, ah[1][1], h0.z, h0.w);
            MMA(d0, ah[0][2], h1.x, h1.y); MMA(d1, ah[1][2], h1.x, h1.y);
            MMA(d0, ah[0][3], h1.z, h1.w); MMA(d1, ah[1][3], h1.z, h1.w);

            UPD(0, d0[0], n0); UPD(0, d0[1], n0 + 1);
            UPD(1, d0[2], n0); UPD(1, d0[3], n0 + 1);
            UPD(2, d1[0], n0); UPD(2, d1[1], n0 + 1);
            UPD(3, d1[2], n0); UPD(3, d1[3], n0 + 1);
        }
        asm volatile("cp.async.wait_group 0;" ::: "memory");
        __syncthreads();
    }

    // ---- dump all 16 per-pixel candidates (4 lanes x top-4) into the pool ----
    int   (*s_cand)[NCAND] = (int(*)[NCAND])s_pool;                 // 16 KB
    float (*s_scA)[NCAND]  = (float(*)[NCAND])(s_pool + 16384);    // 16 KB
#pragma unroll
    for (int p = 0; p < 4; p++) {
        int row = g + (p & 1) * 8 + (p >> 1) * 16;
        int pr = w * 32 + row;
        s_cand[pr][4 * m]     = ii[p];
        s_cand[pr][4 * m + 1] = jj[p];
        s_cand[pr][4 * m + 2] = kk[p];
        s_cand[pr][4 * m + 3] = ll[p];
        s_scA[pr][4 * m]      = bb[p];
        s_scA[pr][4 * m + 1]  = ss[p];
        s_scA[pr][4 * m + 2]  = tt[p];
        s_scA[pr][4 * m + 3]  = qq[p];
    }
    __syncthreads();

    // ---- per-pixel exact rescue (R1-replica comparator) ----
    const int pixel = blockpix + tid;
    const int hw = pixel & (HWDIM - 1);
    const float* xp = xb + hw;
    float z[CD];
#pragma unroll
    for (int c = 0; c < CD; c++) z[c] = __ldg(xp + (size_t)c * HWDIM);

    int   cand[NCAND];
    float sc[NCAND];
#pragma unroll
    for (int i = 0; i < NCAND; i++) { cand[i] = s_cand[tid][i]; sc[i] = s_scA[tid][i]; }

    // approx-min with first-index tie-break
    float mb = sc[0]; int win = cand[0];
#pragma unroll
    for (int i = 1; i < NCAND; i++)
        if (sc[i] < mb || (sc[i] == mb && cand[i] < win)) { mb = sc[i]; win = cand[i]; }

    int nq = 0;
#pragma unroll
    for (int i = 0; i < NCAND; i++) nq += (sc[i] <= mb + EPS);
    if (nq > 1) {
        // exact rescoring: 4 independent fma chains over c%4, merged
        // (p0+p1)+(p2+p3); score = hn - dot  (R1-replica, known-good)
        float be = 3.4e38f; int bw = 0x7fffffff;
#pragma unroll 1
        for (int i = 0; i < NCAND; i++) {
            if (sc[i] <= mb + EPS) {
                const float* er = emb + (size_t)cand[i] * CD;
                float p0 = 0.f, p1 = 0.f, p2 = 0.f, p3 = 0.f;
#pragma unroll
                for (int q = 0; q < CD / 4; q++) {
                    p0 = fmaf(z[4*q],     er[4*q],     p0);
                    p1 = fmaf(z[4*q + 1], er[4*q + 1], p1);
                    p2 = fmaf(z[4*q + 2], er[4*q + 2], p2);
                    p3 = fmaf(z[4*q + 3], er[4*q + 3], p3);
                }
                float dot = __fadd_rn(__fadd_rn(p0, p1), __fadd_rn(p2, p3));
                float se  = __fsub_rn(s_hn[cand[i]], dot);
                if (se < be || (se == be && cand[i] < bw)) { be = se; bw = cand[i]; }
            }
        }
        win = bw;
    }

    // ---- outputs ----
    const float4* erow = (const float4*)(emb + (size_t)win * CD);
    float lsum = 0.f;
#pragma unroll
    for (int i = 0; i < CD / 4; i++) {
        float4 ev = erow[i];
        float x0 = z[4*i], x1 = z[4*i+1], x2 = z[4*i+2], x3 = z[4*i+3];
        size_t base = ((size_t)b * CD + 4 * i) * HWDIM + hw;
        out[base]             = x0 + (ev.x - x0);
        out[base + HWDIM]     = x1 + (ev.y - x1);
        out[base + 2 * HWDIM] = x2 + (ev.z - x2);
        out[base + 3 * HWDIM] = x3 + (ev.w - x3);
        float e0 = x0 - ev.x, e1 = x1 - ev.y, e2 = x2 - ev.z, e3 = x3 - ev.w;
        lsum += e0 * e0 + e1 * e1 + e2 * e2 + e3 * e3;
    }
#pragma unroll
    for (int off = 16; off > 0; off >>= 1)
        lsum += __shfl_down_sync(0xffffffffu, lsum, off);
    if (l == 0) s_red[w] = lsum;
    __syncthreads();
    if (tid < 8) {
        float v = s_red[tid];
#pragma unroll
        for (int off = 4; off > 0; off >>= 1)
            v += __shfl_down_sync(0x000000ffu, v, off);
        if (tid == 0) atomicAdd(&g_loss, v);
    }
    if (IDX_OFF + pixel < out_size) out[IDX_OFF + pixel] = (float)win;
}

__global__ void vq_fin(float* out, int out_size) {
    if (out_size > LOSS_OFF)
        out[LOSS_OFF] = 1.25f * g_loss * (1.0f / 8388608.0f);
}

extern "C" void kernel_launch(void* const* d_in, const int* in_sizes, int n_in,
                              void* d_out, int out_size) {
    const float* x   = (const float*)d_in[0];
    const float* emb = (const float*)d_in[1];
    float* out = (float*)d_out;

    vq_prep<<<16, 256>>>(emb);
    vq_mma<<<NPIX / TPB, TPB>>>(x, emb, out, out_size);
    vq_fin<<<1, 1>>>(out, out_size);
}

// round 10
// speedup vs baseline: 4.4779x; 1.5439x over previous
#include <cuda_runtime.h>
#include <cuda_fp16.h>
#include <cstdint>
#include <cstring>

#define KCODES 1024
#define CD     64
#define NPIX   131072
#define HWDIM  4096
#define TPB    256
#define LOSS_OFF 8388608
#define IDX_OFF  8388609
#define NCHUNK 16            // 16 chunks x 64 codes
#define TPC    8             // tiles (of 8 codes) per chunk
#define EPS    0.30f
#define NCAND  16
#define SOFF   128.0f        // score offset making packed keys positive

__device__ float g_halfnorm[KCODES];
__device__ float g_loss;
__device__ int   g_done = 0;
// fragment-ordered fp16 codebook: [tile(128)][lane(32)][2 x uint4]
__device__ __align__(16) uint4 g_Bh[128 * 32 * 2];

static __device__ __forceinline__ uint32_t smem_u32(const void* p) {
    uint32_t a;
    asm("{ .reg .u64 t; cvta.to.shared.u64 t, %1; cvt.u32.u64 %0, t; }" : "=r"(a) : "l"(p));
    return a;
}
static __device__ __forceinline__ void cp_async16(uint32_t s, const void* g) {
    asm volatile("cp.async.ca.shared.global [%0], [%1], 16;" :: "r"(s), "l"(g) : "memory");
}
static __device__ __forceinline__ uint32_t hpack(float a, float b) {
    __half2 h = __floats2half2_rn(a, b);
    uint32_t u; memcpy(&u, &h, 4); return u;
}

#define MMA(d, a, bx, by)                                                          \
    asm volatile("mma.sync.aligned.m16n8k16.row.col.f32.f16.f16.f32 "              \
        "{%0,%1,%2,%3},{%4,%5,%6,%7},{%8,%9},{%0,%1,%2,%3};"                       \
        : "+f"(d[0]), "+f"(d[1]), "+f"(d[2]), "+f"(d[3])                           \
        : "r"(a[0]), "r"(a[1]), "r"(a[2]), "r"(a[3]), "r"(bx), "r"(by))

// branch-free per-lane top-4 insert of packed (score|index) key
#define UPDK(p, v, n)                                                              \
    { uint32_t key = (__float_as_uint(v) & 0xFFFFFC00u) | (uint32_t)(n);           \
      uint32_t a0 = min(k1[p], key), b0 = max(k1[p], key); k1[p] = a0;             \
      uint32_t a1 = min(k2[p], b0),  b1 = max(k2[p], b0);  k2[p] = a1;             \
      uint32_t a2 = min(k3[p], b1),  b2 = max(k3[p], b1);  k3[p] = a2;             \
      k4[p] = min(k4[p], b2); }

// ---- prep: halfnorms (R1-replica arithmetic) + fragment-ordered fp16 codebook --
__global__ void vq_prep(const float* __restrict__ emb) {
    int t = blockIdx.x * blockDim.x + threadIdx.x;   // 4096 threads
    if (t == 0) g_loss = 0.f;
    if (t < KCODES) {
        const float4* row = (const float4*)(emb + (size_t)t * CD);
        float s = 0.f;
#pragma unroll
        for (int i = 0; i < CD / 4; i++) {
            float4 v = row[i];
            s += v.x * v.x + v.y * v.y + v.z * v.z + v.w * v.w;
        }
        g_halfnorm[t] = 0.5f * s;
    }
    int tile = t >> 5, l = t & 31, m = l & 3;
    int code = tile * 8 + (l >> 2);
    const float* e = emb + (size_t)code * CD;
    uint32_t h[8];
#pragma unroll
    for (int s = 0; s < 4; s++) {
        int c0 = 16 * s + 2 * m;
        h[2 * s]     = hpack(e[c0],     e[c0 + 1]);
        h[2 * s + 1] = hpack(e[c0 + 8], e[c0 + 9]);
    }
    int base = (tile * 32 + l) * 2;
    g_Bh[base]     = make_uint4(h[0], h[1], h[2], h[3]);
    g_Bh[base + 1] = make_uint4(h[4], h[5], h[6], h[7]);
}

// ---- main: fp16 HMMA screen + packed-key top-4 + exact R1-replica rescue ----
__global__ __launch_bounds__(TPB, 2)
void vq_mma(const float* __restrict__ x, const float* __restrict__ emb,
            float* __restrict__ out, int out_size)
{
    // 32 KB pool: B double-buffer (2 x 8 KB) during loop; candidate keys after
    __shared__ __align__(16) unsigned char s_pool[32768];
    __shared__ float s_hn[KCODES];      // exact (rescue comparator)
    __shared__ float s_hnOff[KCODES];   // hn + SOFF (accumulator init)
    __shared__ float s_red[8];

    const int tid = threadIdx.x;
    const int w = tid >> 5, l = tid & 31, g = l >> 2, m = l & 3;
    const int blockpix = blockIdx.x << 8;
    const int b = blockpix >> 12;
    const int hwbase = (blockpix & (HWDIM - 1)) + (w << 5);
    const float* xb = x + (size_t)b * CD * HWDIM;

    // ---- build A fragments (negated z, fp16) ----
    uint32_t ah[2][4][4];
#pragma unroll
    for (int ri = 0; ri < 4; ri++) {
        const int mt = ri >> 1, rr = ri & 1;
        const float* xp = xb + hwbase + g + rr * 8 + mt * 16;
#pragma unroll
        for (int s = 0; s < 4; s++) {
            int c0 = 16 * s + 2 * m;
            float f0 = -__ldg(xp + (size_t)c0 * HWDIM);
            float f1 = -__ldg(xp + (size_t)(c0 + 1) * HWDIM);
            float f2 = -__ldg(xp + (size_t)(c0 + 8) * HWDIM);
            float f3 = -__ldg(xp + (size_t)(c0 + 9) * HWDIM);
            ah[mt][s][rr]     = hpack(f0, f1);
            ah[mt][s][2 + rr] = hpack(f2, f3);
        }
    }

    // halfnorms to smem (exact + offset copy)
#pragma unroll
    for (int i = 0; i < 4; i++) {
        float h = g_halfnorm[tid + i * TPB];
        s_hn[tid + i * TPB]    = h;
        s_hnOff[tid + i * TPB] = h + SOFF;
    }

    // prefetch chunk 0 (8 KB: 2 uint4 per thread)
    {
        uint32_t dh = smem_u32(s_pool) + tid * 32;
        const uint4* sh = g_Bh + tid * 2;
        cp_async16(dh, sh); cp_async16(dh + 16, sh + 1);
        asm volatile("cp.async.commit_group;" ::: "memory");
    }
    asm volatile("cp.async.wait_group 0;" ::: "memory");
    __syncthreads();

    uint32_t k1[4] = {0xFFFFFFFFu,0xFFFFFFFFu,0xFFFFFFFFu,0xFFFFFFFFu};
    uint32_t k2[4] = {0xFFFFFFFFu,0xFFFFFFFFu,0xFFFFFFFFu,0xFFFFFFFFu};
    uint32_t k3[4] = {0xFFFFFFFFu,0xFFFFFFFFu,0xFFFFFFFFu,0xFFFFFFFFu};
    uint32_t k4[4] = {0xFFFFFFFFu,0xFFFFFFFFu,0xFFFFFFFFu,0xFFFFFFFFu};

#pragma unroll 1
    for (int ch = 0; ch < NCHUNK; ch++) {
        const int buf = ch & 1;
        if (ch + 1 < NCHUNK) {   // async prefetch next chunk
            uint32_t dh = smem_u32(s_pool) + (buf ^ 1) * 8192 + tid * 32;
            const uint4* sh = g_Bh + (ch + 1) * 512 + tid * 2;
            cp_async16(dh, sh); cp_async16(dh + 16, sh + 1);
            asm volatile("cp.async.commit_group;" ::: "memory");
        }

        const uint4* bhp = (const uint4*)(s_pool + buf * 8192);
#pragma unroll
        for (int t = 0; t < TPC; t++) {
            uint4 h0 = bhp[t * 64 + l * 2];
            uint4 h1 = bhp[t * 64 + l * 2 + 1];
            const int n0 = ch * 64 + t * 8 + 2 * m;
            float2 hp = *(const float2*)&s_hnOff[n0];

            float d0[4], d1[4];
            d0[0] = hp.x; d0[1] = hp.y; d0[2] = hp.x; d0[3] = hp.y;
            d1[0] = hp.x; d1[1] = hp.y; d1[2] = hp.x; d1[3] = hp.y;

            MMA(d0, ah[0][0], h0.x, h0.y); MMA(d1, ah[1][0], h0.x, h0.y);
            MMA(d0, ah[0][1], h0.z, h0.w); MMA(d1, ah[1][1], h0.z, h0.w);
            MMA(d0, ah[0][2], h1.x, h1.y); MMA(d1, ah[1][2], h1.x, h1.y);
            MMA(d0, ah[0][3], h1.z, h1.w); MMA(d1, ah[1][3], h1.z, h1.w);

            UPDK(0, d0[0], n0); UPDK(0, d0[1], n0 + 1);
            UPDK(1, d0[2], n0); UPDK(1, d0[3], n0 + 1);
            UPDK(2, d1[0], n0); UPDK(2, d1[1], n0 + 1);
            UPDK(3, d1[2], n0); UPDK(3, d1[3], n0 + 1);
        }
        asm volatile("cp.async.wait_group 0;" ::: "memory");
        __syncthreads();
    }

    // ---- dump all 16 per-pixel candidate keys (4 lanes x top-4) ----
    uint32_t (*s_keys)[NCAND] = (uint32_t(*)[NCAND])s_pool;   // 16 KB
#pragma unroll
    for (int p = 0; p < 4; p++) {
        int row = g + (p & 1) * 8 + (p >> 1) * 16;
        int pr = w * 32 + row;
        s_keys[pr][4 * m]     = k1[p];
        s_keys[pr][4 * m + 1] = k2[p];
        s_keys[pr][4 * m + 2] = k3[p];
        s_keys[pr][4 * m + 3] = k4[p];
    }
    __syncthreads();

    // ---- per-pixel selection + exact R1-replica rescue ----
    const int pixel = blockpix + tid;
    const int hw = pixel & (HWDIM - 1);
    const float* xp = xb + hw;
    float z[CD];
#pragma unroll
    for (int c = 0; c < CD; c++) z[c] = __ldg(xp + (size_t)c * HWDIM);

    uint32_t key[NCAND];
#pragma unroll
    for (int i = 0; i < NCAND; i++) key[i] = s_keys[tid][i];

    uint32_t kmin = key[0];
#pragma unroll
    for (int i = 1; i < NCAND; i++) kmin = min(kmin, key[i]);
    int win = kmin & 1023;
    float smin = __uint_as_float(kmin & 0xFFFFFC00u);

    int nq = 0;
#pragma unroll
    for (int i = 0; i < NCAND; i++)
        nq += (__uint_as_float(key[i] & 0xFFFFFC00u) <= smin + EPS);
    if (nq > 1) {
        // exact rescoring: 4 independent fma chains over c%4, merged
        // (p0+p1)+(p2+p3); score = hn - dot  (R1-replica, known-good)
        float be = 3.4e38f; int bw = 0x7fffffff;
#pragma unroll 1
        for (int i = 0; i < NCAND; i++) {
            if (__uint_as_float(key[i] & 0xFFFFFC00u) <= smin + EPS) {
                int ci = key[i] & 1023;
                const float* er = emb + (size_t)ci * CD;
                float p0 = 0.f, p1 = 0.f, p2 = 0.f, p3 = 0.f;
#pragma unroll
                for (int q = 0; q < CD / 4; q++) {
                    p0 = fmaf(z[4*q],     er[4*q],     p0);
                    p1 = fmaf(z[4*q + 1], er[4*q + 1], p1);
                    p2 = fmaf(z[4*q + 2], er[4*q + 2], p2);
                    p3 = fmaf(z[4*q + 3], er[4*q + 3], p3);
                }
                float dot = __fadd_rn(__fadd_rn(p0, p1), __fadd_rn(p2, p3));
                float se  = __fsub_rn(s_hn[ci], dot);
                if (se < be || (se == be && ci < bw)) { be = se; bw = ci; }
            }
        }
        win = bw;
    }

    // ---- outputs ----
    const float4* erow = (const float4*)(emb + (size_t)win * CD);
    float lsum = 0.f;
#pragma unroll
    for (int i = 0; i < CD / 4; i++) {
        float4 ev = erow[i];
        float x0 = z[4*i], x1 = z[4*i+1], x2 = z[4*i+2], x3 = z[4*i+3];
        size_t base = ((size_t)b * CD + 4 * i) * HWDIM + hw;
        out[base]             = x0 + (ev.x - x0);
        out[base + HWDIM]     = x1 + (ev.y - x1);
        out[base + 2 * HWDIM] = x2 + (ev.z - x2);
        out[base + 3 * HWDIM] = x3 + (ev.w - x3);
        float e0 = x0 - ev.x, e1 = x1 - ev.y, e2 = x2 - ev.z, e3 = x3 - ev.w;
        lsum += e0 * e0 + e1 * e1 + e2 * e2 + e3 * e3;
    }
#pragma unroll
    for (int off = 16; off > 0; off >>= 1)
        lsum += __shfl_down_sync(0xffffffffu, lsum, off);
    if (l == 0) s_red[w] = lsum;
    __syncthreads();
    if (tid < 8) {
        float v = s_red[tid];
#pragma unroll
        for (int off = 4; off > 0; off >>= 1)
            v += __shfl_down_sync(0x000000ffu, v, off);
        if (tid == 0) {
            atomicAdd(&g_loss, v);
            __threadfence();
            int ticket = atomicAdd(&g_done, 1);
            if (ticket == (int)gridDim.x - 1) {   // last CTA finalizes loss
                if (out_size > LOSS_OFF)
                    out[LOSS_OFF] = 1.25f * (*(volatile float*)&g_loss) * (1.0f / 8388608.0f);
                g_done = 0;                        // reset for next replay
            }
        }
    }
    if (IDX_OFF + pixel < out_size) out[IDX_OFF + pixel] = (float)win;
}

extern "C" void kernel_launch(void* const* d_in, const int* in_sizes, int n_in,
                              void* d_out, int out_size) {
    const float* x   = (const float*)d_in[0];
    const float* emb = (const float*)d_in[1];
    float* out = (float*)d_out;

    vq_prep<<<16, 256>>>(emb);
    vq_mma<<<NPIX / TPB, TPB>>>(x, emb, out, out_size);
}